// round 6
// baseline (speedup 1.0000x reference)
#include <cuda_runtime.h>
#include <cuda_bf16.h>

// Problem constants (match reference)
#define Nn 50000
#define Ee 640000
#define Hh 128
#define Gg 64
#define Oo 16

#define SCAN_B 512
#define SCAN_NB ((Nn + SCAN_B - 1) / SCAN_B)   // 98

// Scratch (static __device__ — no allocs allowed)
__device__ float g_deg[Nn];
__device__ float g_dinv[Nn];
__device__ float g_xw[(size_t)Nn * Hh];
__device__ float g_h[(size_t)Nn * Hh];
__device__ float g_pool[Gg * Hh];
__device__ float g_cnt[Gg];

// CSR scratch
__device__ int    g_count[Nn];
__device__ int    g_cursor[Nn];
__device__ int    g_scan[Nn];
__device__ int    g_bsum[SCAN_NB];
__device__ int    g_boff[SCAN_NB];
__device__ int    g_rowptr[Nn + 1];
__device__ float2 g_csr[Ee];        // .x = src index (int bits), .y = coef

// ---------------- f32x2 packed helpers ----------------

__device__ __forceinline__ unsigned long long pack2(float v) {
    unsigned long long r;
    unsigned int u = __float_as_uint(v);
    asm("mov.b64 %0, {%1, %1};" : "=l"(r) : "r"(u));
    return r;
}

#define FMA2(d, a, b) \
    asm("fma.rn.f32x2 %0, %1, %2, %0;" : "+l"(d) : "l"(a), "l"(b))

// ---------------- init ----------------

__global__ void init_node_kernel() {
    int i = blockIdx.x * blockDim.x + threadIdx.x;
    if (i < Nn) {
        g_deg[i] = 1.0f;   // self-loop weight 1
        g_count[i] = 0;
        g_cursor[i] = 0;
    }
    if (i < Gg * Hh) g_pool[i] = 0.0f;
    if (i < Gg) g_cnt[i] = 0.0f;
}

// histogram: weighted degree (float) + edge count (int) per destination
__global__ void deg_count_kernel(const int* __restrict__ col,
                                 const float* __restrict__ ew) {
    int e = blockIdx.x * blockDim.x + threadIdx.x;
    if (e < Ee) {
        int c = col[e];
        atomicAdd(&g_deg[c], ew[e]);
        atomicAdd(&g_count[c], 1);
    }
}

// ---------------- scan (exclusive prefix over g_count -> g_rowptr) --------
// dinv computation fused in (deg is final by the time this runs).

__global__ void scan_block_kernel() {
    __shared__ int sh[SCAN_B];
    int tid = threadIdx.x;
    int i = blockIdx.x * SCAN_B + tid;
    if (i < Nn) {
        float d = g_deg[i];
        g_dinv[i] = (d > 0.0f) ? rsqrtf(d) : 0.0f;
    }
    int v = (i < Nn) ? g_count[i] : 0;
    sh[tid] = v;
    __syncthreads();
#pragma unroll
    for (int o = 1; o < SCAN_B; o <<= 1) {
        int t = (tid >= o) ? sh[tid - o] : 0;
        __syncthreads();
        sh[tid] += t;
        __syncthreads();
    }
    if (i < Nn) g_scan[i] = sh[tid];   // inclusive within block
    if (tid == SCAN_B - 1) g_bsum[blockIdx.x] = sh[tid];
}

__global__ void scan_bsum_kernel() {
    __shared__ int sh[128];
    int tid = threadIdx.x;
    int v = (tid < SCAN_NB) ? g_bsum[tid] : 0;
    sh[tid] = v;
    __syncthreads();
#pragma unroll
    for (int o = 1; o < 128; o <<= 1) {
        int t = (tid >= o) ? sh[tid - o] : 0;
        __syncthreads();
        sh[tid] += t;
        __syncthreads();
    }
    if (tid < SCAN_NB) g_boff[tid] = sh[tid] - v;  // exclusive
}

__global__ void scan_final_kernel() {
    int i = blockIdx.x * blockDim.x + threadIdx.x;
    if (i < Nn) {
        g_rowptr[i + 1] = g_scan[i] + g_boff[i / SCAN_B];
        if (i == 0) g_rowptr[0] = 0;
    }
}

// fill CSR: for each edge, place packed (src, coef) into dst's segment
__global__ void csr_fill_kernel(const int* __restrict__ row,
                                const int* __restrict__ col,
                                const float* __restrict__ ew) {
    int e = blockIdx.x * blockDim.x + threadIdx.x;
    if (e >= Ee) return;
    int r = row[e];
    int c = col[e];
    int p = g_rowptr[c] + atomicAdd(&g_cursor[c], 1);
    g_csr[p] = make_float2(__int_as_float(r), g_dinv[r] * ew[e] * g_dinv[c]);
}

// ---------------- GEMM via packed f32x2 FMA -------------------------------
// g_xw[n,128] = A[n,128] @ W[128,128]; A==nullptr -> read g_h.
// BM=128, BN=128, BK=8; 256 threads; 8 rows x 8 cols per thread.
// Accumulators hold 2 adjacent M-rows packed in one f32x2 register.
// W tile stored pre-duplicated {w,w}; columns per thread strided by 16
// so W LDS.64 phases are 128B-contiguous (conflict-free).

__global__ void __launch_bounds__(256)
gemm128_f32x2_kernel(const float* __restrict__ A,
                     const float* __restrict__ W, int n) {
    __shared__ float Xs[8][128];                 // [k][m]
    __shared__ unsigned long long Wd[8][128];    // [k][c] duplicated

    const float* src = A ? A : (const float*)g_h;

    const int tid = threadIdx.x;
    const int block_row = blockIdx.x * 128;
    const int ty = tid >> 4;          // 0..15
    const int tx = tid & 15;          // 0..15
    const int rows8 = ty * 8;

    unsigned long long acc2[4][8];
#pragma unroll
    for (int i = 0; i < 4; i++)
#pragma unroll
        for (int j = 0; j < 8; j++) acc2[i][j] = 0ull;

    const int lrow = tid >> 1;          // 0..127 A-tile row to load
    const int lkq = (tid & 1) * 4;      // k quad within BK=8
    const int wk = tid >> 5;            // 0..7 W-tile k row
    const int wc = (tid & 31) * 4;      // W col quad

    for (int k0 = 0; k0 < 128; k0 += 8) {
        int gr = block_row + lrow;
        float4 v = make_float4(0.f, 0.f, 0.f, 0.f);
        if (gr < n) v = *(const float4*)(src + (size_t)gr * 128 + k0 + lkq);
        Xs[lkq + 0][lrow] = v.x;
        Xs[lkq + 1][lrow] = v.y;
        Xs[lkq + 2][lrow] = v.z;
        Xs[lkq + 3][lrow] = v.w;

        float4 w = *(const float4*)(W + (size_t)(k0 + wk) * 128 + wc);
        Wd[wk][wc + 0] = pack2(w.x);
        Wd[wk][wc + 1] = pack2(w.y);
        Wd[wk][wc + 2] = pack2(w.z);
        Wd[wk][wc + 3] = pack2(w.w);
        __syncthreads();

#pragma unroll
        for (int k = 0; k < 8; k++) {
            ulonglong2 xa = *(const ulonglong2*)&Xs[k][rows8];
            ulonglong2 xb = *(const ulonglong2*)&Xs[k][rows8 + 4];
            unsigned long long x0 = xa.x, x1 = xa.y, x2v = xb.x, x3 = xb.y;
#pragma unroll
            for (int j = 0; j < 8; j++) {
                unsigned long long wv = Wd[k][tx + j * 16];
                FMA2(acc2[0][j], x0, wv);
                FMA2(acc2[1][j], x1, wv);
                FMA2(acc2[2][j], x2v, wv);
                FMA2(acc2[3][j], x3, wv);
            }
        }
        __syncthreads();
    }

#pragma unroll
    for (int rp = 0; rp < 4; rp++) {
        int r0 = block_row + rows8 + rp * 2;
#pragma unroll
        for (int j = 0; j < 8; j++) {
            unsigned int lo, hi;
            asm("mov.b64 {%0,%1}, %2;" : "=r"(lo), "=r"(hi) : "l"(acc2[rp][j]));
            int c = tx + j * 16;
            if (r0 < n) g_xw[(size_t)r0 * 128 + c] = __uint_as_float(lo);
            if (r0 + 1 < n) g_xw[(size_t)(r0 + 1) * 128 + c] = __uint_as_float(hi);
        }
    }
}

// ---------------- gather core (unroll x8, packed CSR) ----------------------

__device__ __forceinline__ float4 gather_node(int node, int lane,
                                              const float* __restrict__ b) {
    int p = g_rowptr[node];
    const int end = g_rowptr[node + 1];

    float di = g_dinv[node];
    float d2 = di * di;
    float4 sv = ((const float4*)(g_xw + (size_t)node * Hh))[lane];
    float ax = sv.x * d2, ay = sv.y * d2, az = sv.z * d2, aw = sv.w * d2;

#pragma unroll 1
    for (; p + 7 < end; p += 8) {
        float2 e[8];
#pragma unroll
        for (int u = 0; u < 8; u++) e[u] = g_csr[p + u];
        float4 v[8];
#pragma unroll
        for (int u = 0; u < 8; u++)
            v[u] = ((const float4*)(g_xw + (size_t)__float_as_int(e[u].x) * Hh))[lane];
#pragma unroll
        for (int u = 0; u < 8; u++) {
            ax += e[u].y * v[u].x;
            ay += e[u].y * v[u].y;
            az += e[u].y * v[u].z;
            aw += e[u].y * v[u].w;
        }
    }
#pragma unroll 1
    for (; p + 3 < end; p += 4) {
        float2 e[4];
#pragma unroll
        for (int u = 0; u < 4; u++) e[u] = g_csr[p + u];
#pragma unroll
        for (int u = 0; u < 4; u++) {
            float4 v = ((const float4*)(g_xw + (size_t)__float_as_int(e[u].x) * Hh))[lane];
            ax += e[u].y * v.x;
            ay += e[u].y * v.y;
            az += e[u].y * v.z;
            aw += e[u].y * v.w;
        }
    }
#pragma unroll 1
    for (; p < end; p++) {
        float2 e0 = g_csr[p];
        float4 v0 = ((const float4*)(g_xw + (size_t)__float_as_int(e0.x) * Hh))[lane];
        ax += e0.y * v0.x;
        ay += e0.y * v0.y;
        az += e0.y * v0.z;
        aw += e0.y * v0.w;
    }

    float4 bv = *(const float4*)(b + lane * 4);
    return make_float4(fmaxf(ax + bv.x, 0.0f), fmaxf(ay + bv.y, 0.0f),
                       fmaxf(az + bv.z, 0.0f), fmaxf(aw + bv.w, 0.0f));
}

// layer 1: g_h[node] = relu(agg + dinv^2*xw + b1)
__global__ void gather1_kernel(const float* __restrict__ b) {
    int node = blockIdx.x * 8 + (threadIdx.x >> 5);
    if (node >= Nn) return;
    int lane = threadIdx.x & 31;
    float4 acc = gather_node(node, lane, b);
    ((float4*)(g_h + (size_t)node * Hh))[lane] = acc;
}

// layer 2 fused with pooling: h2 never materialized
__global__ void gather2_pool_kernel(const float* __restrict__ b,
                                    const int* __restrict__ batch) {
    int node = blockIdx.x * 8 + (threadIdx.x >> 5);
    if (node >= Nn) return;
    int lane = threadIdx.x & 31;
    float4 acc = gather_node(node, lane, b);
    int bg = batch[node];
    float* pl = g_pool + bg * Hh + lane * 4;
    atomicAdd(pl + 0, acc.x);
    atomicAdd(pl + 1, acc.y);
    atomicAdd(pl + 2, acc.z);
    atomicAdd(pl + 3, acc.w);
    if (lane == 0) atomicAdd(&g_cnt[bg], 1.0f);
}

// ---------------- final FC ----------------

__global__ void fc_kernel(float* __restrict__ out,
                          const float* __restrict__ Wfc,
                          const float* __restrict__ bfc) {
    int g = threadIdx.x >> 4;
    int o = threadIdx.x & 15;
    float inv = 1.0f / fmaxf(g_cnt[g], 1.0f);
    float acc = 0.0f;
#pragma unroll 8
    for (int k = 0; k < Hh; k++) acc += g_pool[g * Hh + k] * Wfc[k * Oo + o];
    out[g * Oo + o] = acc * inv + bfc[o];
}

// ---------------- launch ----------------

extern "C" void kernel_launch(void* const* d_in, const int* in_sizes, int n_in,
                              void* d_out, int out_size) {
    const float* x = (const float*)d_in[0];
    const int* edge_index = (const int*)d_in[1];   // int32
    const float* ew = (const float*)d_in[2];
    const int* batch = (const int*)d_in[3];        // int32
    const float* W1 = (const float*)d_in[4];
    const float* b1 = (const float*)d_in[5];
    const float* W2 = (const float*)d_in[6];
    const float* b2 = (const float*)d_in[7];
    const float* Wfc = (const float*)d_in[8];
    const float* bfc = (const float*)d_in[9];
    float* out = (float*)d_out;

    const int* row = edge_index;        // edge_index[0]
    const int* col = edge_index + Ee;   // edge_index[1]

    const int nblk = (Nn + 255) / 256;
    const int eblk = (Ee + 255) / 256;
    const int gemm_blocks = (Nn + 127) / 128;
    const int warp8_blocks = (Nn + 7) / 8;

    // degree + CSR build
    init_node_kernel<<<nblk, 256>>>();
    deg_count_kernel<<<eblk, 256>>>(col, ew);
    scan_block_kernel<<<SCAN_NB, SCAN_B>>>();   // also computes dinv
    scan_bsum_kernel<<<1, 128>>>();
    scan_final_kernel<<<nblk, 256>>>();
    csr_fill_kernel<<<eblk, 256>>>(row, col, ew);

    // layer 1: xw = x@W1 ; h = relu(gather(xw) + dinv^2*xw + b1)
    gemm128_f32x2_kernel<<<gemm_blocks, 256>>>(x, W1, Nn);
    gather1_kernel<<<warp8_blocks, 256>>>(b1);

    // layer 2: xw = h@W2 ; pooled gather (no h2 materialization)
    gemm128_f32x2_kernel<<<gemm_blocks, 256>>>(nullptr, W2, Nn);
    gather2_pool_kernel<<<warp8_blocks, 256>>>(b2, batch);

    // fc
    fc_kernel<<<1, Gg * Oo>>>(out, Wfc, bfc);
}

// round 7
// speedup vs baseline: 1.1403x; 1.1403x over previous
#include <cuda_runtime.h>
#include <cuda_bf16.h>

// Problem constants (match reference)
#define Nn 50000
#define Ee 640000
#define Hh 128
#define Gg 64
#define Oo 16

#define SCAN_B 512
#define SCAN_NB ((Nn + SCAN_B - 1) / SCAN_B)   // 98

// Scratch (static __device__ — no allocs allowed)
__device__ float g_deg[Nn];
__device__ float g_dinv[Nn];
__device__ float g_xw[(size_t)Nn * Hh];
__device__ float g_h[(size_t)Nn * Hh];
__device__ float g_pool[Gg * Hh];
__device__ float g_cnt[Gg];

// CSR scratch
__device__ int    g_count[Nn];
__device__ int    g_cursor[Nn];
__device__ int    g_scan[Nn];
__device__ int    g_bsum[SCAN_NB];
__device__ int    g_boff[SCAN_NB];
__device__ int    g_rowptr[Nn + 1];
__device__ float2 g_csr[Ee];        // .x = src index (int bits), .y = coef

// ---------------- init ----------------

__global__ void init_node_kernel() {
    int i = blockIdx.x * blockDim.x + threadIdx.x;
    if (i < Nn) {
        g_deg[i] = 1.0f;   // self-loop weight 1
        g_count[i] = 0;
        g_cursor[i] = 0;
    }
    if (i < Gg * Hh) g_pool[i] = 0.0f;
    if (i < Gg) g_cnt[i] = 0.0f;
}

// histogram: weighted degree (float) + edge count (int) per destination
__global__ void deg_count_kernel(const int* __restrict__ col,
                                 const float* __restrict__ ew) {
    int e = blockIdx.x * blockDim.x + threadIdx.x;
    if (e < Ee) {
        int c = col[e];
        atomicAdd(&g_deg[c], ew[e]);
        atomicAdd(&g_count[c], 1);
    }
}

// ---------------- scan (exclusive prefix over g_count -> g_rowptr) --------
// dinv computation fused in (deg is final by the time this runs).

__global__ void scan_block_kernel() {
    __shared__ int sh[SCAN_B];
    int tid = threadIdx.x;
    int i = blockIdx.x * SCAN_B + tid;
    if (i < Nn) {
        float d = g_deg[i];
        g_dinv[i] = (d > 0.0f) ? rsqrtf(d) : 0.0f;
    }
    int v = (i < Nn) ? g_count[i] : 0;
    sh[tid] = v;
    __syncthreads();
#pragma unroll
    for (int o = 1; o < SCAN_B; o <<= 1) {
        int t = (tid >= o) ? sh[tid - o] : 0;
        __syncthreads();
        sh[tid] += t;
        __syncthreads();
    }
    if (i < Nn) g_scan[i] = sh[tid];   // inclusive within block
    if (tid == SCAN_B - 1) g_bsum[blockIdx.x] = sh[tid];
}

__global__ void scan_bsum_kernel() {
    __shared__ int sh[128];
    int tid = threadIdx.x;
    int v = (tid < SCAN_NB) ? g_bsum[tid] : 0;
    sh[tid] = v;
    __syncthreads();
#pragma unroll
    for (int o = 1; o < 128; o <<= 1) {
        int t = (tid >= o) ? sh[tid - o] : 0;
        __syncthreads();
        sh[tid] += t;
        __syncthreads();
    }
    if (tid < SCAN_NB) g_boff[tid] = sh[tid] - v;  // exclusive
}

__global__ void scan_final_kernel() {
    int i = blockIdx.x * blockDim.x + threadIdx.x;
    if (i < Nn) {
        g_rowptr[i + 1] = g_scan[i] + g_boff[i / SCAN_B];
        if (i == 0) g_rowptr[0] = 0;
    }
}

// fill CSR: for each edge, place packed (src, coef) into dst's segment
__global__ void csr_fill_kernel(const int* __restrict__ row,
                                const int* __restrict__ col,
                                const float* __restrict__ ew) {
    int e = blockIdx.x * blockDim.x + threadIdx.x;
    if (e >= Ee) return;
    int r = row[e];
    int c = col[e];
    int p = g_rowptr[c] + atomicAdd(&g_cursor[c], 1);
    g_csr[p] = make_float2(__int_as_float(r), g_dinv[r] * ew[e] * g_dinv[c]);
}

// ---------------- GEMM: g_xw[n,128] = A[n,128] @ W[128,128] ----------------
// A == nullptr means "read from g_h". (proven R3-R5 kernel: 47.6us, at the
// FFMA-3reg SIMT roofline)

__global__ void gemm128_kernel(const float* __restrict__ A,
                               const float* __restrict__ W, int n) {
    __shared__ float Xs[32][64];    // [k][m] (transposed)
    __shared__ float Ws[32][128];   // [k][c]

    const float* src = A ? A : (const float*)g_h;

    const int tid = threadIdx.x;
    const int block_row = blockIdx.x * 64;
    const int cg = tid & 31;
    const int rg = tid >> 5;

    float acc[8][4];
#pragma unroll
    for (int i = 0; i < 8; i++)
#pragma unroll
        for (int j = 0; j < 4; j++) acc[i][j] = 0.0f;

    const int lr = tid >> 2;
    const int lk = (tid & 3) * 8;

    for (int k0 = 0; k0 < 128; k0 += 32) {
        float4 v0, v1;
        int grow = block_row + lr;
        if (grow < n) {
            const float4* p = (const float4*)(src + (size_t)grow * 128 + k0 + lk);
            v0 = p[0];
            v1 = p[1];
        } else {
            v0 = make_float4(0.f, 0.f, 0.f, 0.f);
            v1 = v0;
        }
        Xs[lk + 0][lr] = v0.x; Xs[lk + 1][lr] = v0.y;
        Xs[lk + 2][lr] = v0.z; Xs[lk + 3][lr] = v0.w;
        Xs[lk + 4][lr] = v1.x; Xs[lk + 5][lr] = v1.y;
        Xs[lk + 6][lr] = v1.z; Xs[lk + 7][lr] = v1.w;

#pragma unroll
        for (int i = 0; i < 4; i++) {
            int idx = tid + i * 256;
            int kk = idx >> 5;
            int cc = (idx & 31) * 4;
            *(float4*)&Ws[kk][cc] = *(const float4*)(W + (size_t)(k0 + kk) * 128 + cc);
        }
        __syncthreads();

#pragma unroll
        for (int k = 0; k < 32; k++) {
            float4 wf = *(float4*)&Ws[k][cg * 4];
            float4 x0 = *(float4*)&Xs[k][rg * 8];
            float4 x1 = *(float4*)&Xs[k][rg * 8 + 4];
            float xf[8] = {x0.x, x0.y, x0.z, x0.w, x1.x, x1.y, x1.z, x1.w};
#pragma unroll
            for (int i = 0; i < 8; i++) {
                acc[i][0] += xf[i] * wf.x;
                acc[i][1] += xf[i] * wf.y;
                acc[i][2] += xf[i] * wf.z;
                acc[i][3] += xf[i] * wf.w;
            }
        }
        __syncthreads();
    }

#pragma unroll
    for (int i = 0; i < 8; i++) {
        int r = block_row + rg * 8 + i;
        if (r < n)
            *(float4*)(g_xw + (size_t)r * 128 + cg * 4) =
                make_float4(acc[i][0], acc[i][1], acc[i][2], acc[i][3]);
    }
}

// ---------------- gather core: predicated x8 blocks, no scalar tail --------
// Every iteration issues 8 CSR loads + 8 row gathers (MLP=8). Out-of-range
// slots clamp the read index into the segment (in-bounds, L1-hit) and zero
// the coefficient.

__device__ __forceinline__ float4 gather_node(int node, int lane,
                                              const float* __restrict__ b) {
    const int start = g_rowptr[node];
    const int end = g_rowptr[node + 1];
    const int cnt = end - start;

    float di = g_dinv[node];
    float d2 = di * di;
    float4 sv = ((const float4*)(g_xw + (size_t)node * Hh))[lane];
    float ax = sv.x * d2, ay = sv.y * d2, az = sv.z * d2, aw = sv.w * d2;

#pragma unroll 1
    for (int blk = 0; blk < cnt; blk += 8) {
        float2 e[8];
        float cf[8];
#pragma unroll
        for (int u = 0; u < 8; u++) {
            int q = blk + u;
            int qs = (q < cnt) ? q : cnt - 1;   // safe clamp (cnt>0 here)
            e[u] = g_csr[start + qs];
            cf[u] = (q < cnt) ? e[u].y : 0.0f;
        }
        float4 v[8];
#pragma unroll
        for (int u = 0; u < 8; u++)
            v[u] = ((const float4*)(g_xw + (size_t)__float_as_int(e[u].x) * Hh))[lane];
#pragma unroll
        for (int u = 0; u < 8; u++) {
            ax += cf[u] * v[u].x;
            ay += cf[u] * v[u].y;
            az += cf[u] * v[u].z;
            aw += cf[u] * v[u].w;
        }
    }

    float4 bv = *(const float4*)(b + lane * 4);
    return make_float4(fmaxf(ax + bv.x, 0.0f), fmaxf(ay + bv.y, 0.0f),
                       fmaxf(az + bv.z, 0.0f), fmaxf(aw + bv.w, 0.0f));
}

// layer 1: g_h[node] = relu(agg + dinv^2*xw + b1)
__global__ void gather1_kernel(const float* __restrict__ b) {
    int node = blockIdx.x * 8 + (threadIdx.x >> 5);
    if (node >= Nn) return;
    int lane = threadIdx.x & 31;
    float4 acc = gather_node(node, lane, b);
    ((float4*)(g_h + (size_t)node * Hh))[lane] = acc;
}

// layer 2 fused with pooling: h2 never materialized
__global__ void gather2_pool_kernel(const float* __restrict__ b,
                                    const int* __restrict__ batch) {
    int node = blockIdx.x * 8 + (threadIdx.x >> 5);
    if (node >= Nn) return;
    int lane = threadIdx.x & 31;
    float4 acc = gather_node(node, lane, b);
    int bg = batch[node];
    float* pl = g_pool + bg * Hh + lane * 4;
    atomicAdd(pl + 0, acc.x);
    atomicAdd(pl + 1, acc.y);
    atomicAdd(pl + 2, acc.z);
    atomicAdd(pl + 3, acc.w);
    if (lane == 0) atomicAdd(&g_cnt[bg], 1.0f);
}

// ---------------- final FC ----------------

__global__ void fc_kernel(float* __restrict__ out,
                          const float* __restrict__ Wfc,
                          const float* __restrict__ bfc) {
    int g = threadIdx.x >> 4;
    int o = threadIdx.x & 15;
    float inv = 1.0f / fmaxf(g_cnt[g], 1.0f);
    float acc = 0.0f;
#pragma unroll 8
    for (int k = 0; k < Hh; k++) acc += g_pool[g * Hh + k] * Wfc[k * Oo + o];
    out[g * Oo + o] = acc * inv + bfc[o];
}

// ---------------- launch ----------------

extern "C" void kernel_launch(void* const* d_in, const int* in_sizes, int n_in,
                              void* d_out, int out_size) {
    const float* x = (const float*)d_in[0];
    const int* edge_index = (const int*)d_in[1];   // int32
    const float* ew = (const float*)d_in[2];
    const int* batch = (const int*)d_in[3];        // int32
    const float* W1 = (const float*)d_in[4];
    const float* b1 = (const float*)d_in[5];
    const float* W2 = (const float*)d_in[6];
    const float* b2 = (const float*)d_in[7];
    const float* Wfc = (const float*)d_in[8];
    const float* bfc = (const float*)d_in[9];
    float* out = (float*)d_out;

    const int* row = edge_index;        // edge_index[0]
    const int* col = edge_index + Ee;   // edge_index[1]

    const int nblk = (Nn + 255) / 256;
    const int eblk = (Ee + 255) / 256;
    const int gemm_blocks = (Nn + 63) / 64;
    const int warp8_blocks = (Nn + 7) / 8;

    // degree + CSR build
    init_node_kernel<<<nblk, 256>>>();
    deg_count_kernel<<<eblk, 256>>>(col, ew);
    scan_block_kernel<<<SCAN_NB, SCAN_B>>>();   // also computes dinv
    scan_bsum_kernel<<<1, 128>>>();
    scan_final_kernel<<<nblk, 256>>>();
    csr_fill_kernel<<<eblk, 256>>>(row, col, ew);

    // layer 1: xw = x@W1 ; h = relu(gather(xw) + dinv^2*xw + b1)
    gemm128_kernel<<<gemm_blocks, 256>>>(x, W1, Nn);
    gather1_kernel<<<warp8_blocks, 256>>>(b1);

    // layer 2: xw = h@W2 ; pooled gather (no h2 materialization)
    gemm128_kernel<<<gemm_blocks, 256>>>(nullptr, W2, Nn);
    gather2_pool_kernel<<<warp8_blocks, 256>>>(b2, batch);

    // fc
    fc_kernel<<<1, Gg * Oo>>>(out, Wfc, bfc);
}